// round 9
// baseline (speedup 1.0000x reference)
#include <cuda_runtime.h>
#include <cuda_fp16.h>
#include <math.h>
#include <stdint.h>

#define N_ROWS 32768
#define D_IN   3000
#define KPAD1  3072
#define H0     1024
#define H1     256
#define K_CL   20

// ---------------- scratch (static device arrays; no allocs) ----------------
__device__ __align__(16) __half g_xh[(size_t)N_ROWS * KPAD1];
__device__ __align__(16) __half g_w1t[(size_t)H0 * KPAD1];
__device__ __align__(16) __half g_hh[(size_t)N_ROWS * H0];
__device__ __align__(16) __half g_w2t[(size_t)H1 * H0];

// ---------------- helpers ----------------
__device__ __forceinline__ uint32_t smem_u32(const void* p) {
    uint32_t a;
    asm("{ .reg .u64 t; cvta.to.shared.u64 t, %1; cvt.u32.u64 %0, t; }" : "=r"(a) : "l"(p));
    return a;
}
__device__ __forceinline__ void cp_async16(uint32_t s, const void* g) {
    asm volatile("cp.async.cg.shared.global [%0], [%1], 16;" :: "r"(s), "l"(g));
}
__device__ __forceinline__ void cp_commit() {
    asm volatile("cp.async.commit_group;" ::: "memory");
}
template <int N>
__device__ __forceinline__ void cp_wait() {
    asm volatile("cp.async.wait_group %0;" :: "n"(N) : "memory");
}
__device__ __forceinline__ void ldm_x4(uint32_t* r, uint32_t addr) {
    asm volatile("ldmatrix.sync.aligned.m8n8.x4.shared.b16 {%0,%1,%2,%3}, [%4];"
        : "=r"(r[0]), "=r"(r[1]), "=r"(r[2]), "=r"(r[3]) : "r"(addr));
}
__device__ __forceinline__ void mma_f16(float* c, const uint32_t* a, const uint32_t* b) {
    asm volatile(
        "mma.sync.aligned.m16n8k16.row.col.f32.f16.f16.f32 "
        "{%0,%1,%2,%3}, {%4,%5,%6,%7}, {%8,%9}, {%0,%1,%2,%3};"
        : "+f"(c[0]), "+f"(c[1]), "+f"(c[2]), "+f"(c[3])
        : "r"(a[0]), "r"(a[1]), "r"(a[2]), "r"(a[3]), "r"(b[0]), "r"(b[1]));
}

// ---------------- preprocess kernels ----------------
__global__ __launch_bounds__(256)
void convert_x_kernel(const float* __restrict__ x,
                      __half* __restrict__ xh)
{
    const int row = blockIdx.x;
    const float* xr = x + (size_t)row * D_IN;
    __half* oh = xh + (size_t)row * KPAD1;
    for (int p = threadIdx.x; p < KPAD1 / 2; p += 256) {
        int c = p * 2;
        float v0 = 0.f, v1 = 0.f;
        if (c < D_IN) {
            float2 v = *reinterpret_cast<const float2*>(xr + c);
            v0 = v.x; v1 = v.y;
        }
        *reinterpret_cast<__half2*>(oh + c) =
            __halves2half2(__float2half_rn(v0), __float2half_rn(v1));
    }
}

// W [K, N] fp32 -> Wt [N, Kpad] fp16 (transposed, zero-padded K)
__global__ __launch_bounds__(256)
void transpose_kernel(const float* __restrict__ W,
                      __half* __restrict__ T,
                      int K, int N, int Kpad)
{
    __shared__ float s[32][33];
    const int k0 = blockIdx.x * 32;
    const int n0 = blockIdx.y * 32;
    const int tx = threadIdx.x, ty = threadIdx.y;
    #pragma unroll
    for (int j = 0; j < 32; j += 8) {
        int k = k0 + ty + j;
        s[ty + j][tx] = (k < K) ? W[(size_t)k * N + n0 + tx] : 0.0f;
    }
    __syncthreads();
    #pragma unroll
    for (int j = 0; j < 32; j += 8) {
        int n = n0 + ty + j;
        int kk = k0 + tx;
        T[(size_t)n * Kpad + kk] = __float2half_rn(s[tx][ty + j]);
    }
}

// ---------------- HMMA single-pass fp16 GEMM ----------------
// CTA tile 128x128, warp tile 64x32 (8 warps, 2x4), K-chunk 64 fp16.
// Stage: [A 16K][B 16K] = 32KB; 3-stage pipeline = 96KB -> 2 CTAs/SM.
// Fragments double-buffered; cp_wait+barrier at ks2/ks3 boundary with
// cross-chunk fragment prefetch so the tensor pipe never idles on LDSM.
#define TILE_A   16384
#define STAGE_B  32768
#define NSTAGE   3
#define GEMM_SMEM (NSTAGE * STAGE_B)   // 98304

template <int KS>
__device__ __forceinline__ void prefetch_frags(
    uint32_t st, const uint32_t* offA0, const uint32_t* offB0,
    uint32_t (*fa)[4], uint32_t (*fb)[2])
{
    constexpr uint32_t kx = KS * 32;
    #pragma unroll
    for (int mt = 0; mt < 4; mt++)
        ldm_x4(fa[mt], (st + offA0[mt]) ^ kx);
    #pragma unroll
    for (int nt2 = 0; nt2 < 2; nt2++) {
        uint32_t r[4];
        ldm_x4(r, (st + TILE_A + offB0[nt2]) ^ kx);
        fb[nt2 * 2][0] = r[0]; fb[nt2 * 2][1] = r[2];
        fb[nt2 * 2 + 1][0] = r[1]; fb[nt2 * 2 + 1][1] = r[3];
    }
}

__device__ __forceinline__ void compute_frags(
    float (*acc)[4][4], uint32_t (*fa)[4], uint32_t (*fb)[2])
{
    #pragma unroll
    for (int mt = 0; mt < 4; mt++)
        #pragma unroll
        for (int nt = 0; nt < 4; nt++)
            mma_f16(acc[mt][nt], fa[mt], fb[nt]);
}

// EPI=0: bias+SiLU -> fp16.  EPI=1: bias -> fp32.
template <int EPI>
__global__ __launch_bounds__(256, 2)
void gemm_mma_kernel(const __half* __restrict__ A,
                     const __half* __restrict__ B,
                     const float* __restrict__ bias,
                     __half* __restrict__ OutH,
                     float* __restrict__ OutF,
                     int Kpad, int NC, int ldOut)
{
    extern __shared__ char smem[];
    const uint32_t sbase = smem_u32(smem);
    const int tid  = threadIdx.x;
    const int wid  = tid >> 5;
    const int lane = tid & 31;
    const int mBase = blockIdx.y * 128;
    const int nBase = blockIdx.x * 128;
    const int warpM = (wid & 1) * 64;    // 0 / 64
    const int warpN = (wid >> 1) * 32;   // 0..96

    // ---- per-thread load geometry (constant across chunks) ----
    const int row_ld = tid >> 3;          // 0..31
    const int c16    = tid & 7;           // 16B column
    const uint32_t swB = (uint32_t)(row_ld * 128 + ((c16 * 16) ^ ((row_ld & 7) << 4)));
    const char* gA = (const char*)(A + (size_t)(mBase + row_ld) * Kpad) + c16 * 16;
    const char* gB = (const char*)(B + (size_t)(nBase + row_ld) * Kpad) + c16 * 16;
    const size_t itStride = (size_t)32 * Kpad * sizeof(__half);   // 32 rows down

    // ---- per-warp ldmatrix base offsets (ks=0); ks variant = off ^ (ks*32) ----
    const int aRowIn = lane & 15;
    const int kHalf  = (lane >> 4) << 4;  // 0 / 16 bytes
    uint32_t offA0[4], offB0[2];
    #pragma unroll
    for (int mt = 0; mt < 4; mt++) {
        int row = warpM + mt * 16 + aRowIn;
        offA0[mt] = (uint32_t)(row * 128 + (kHalf ^ ((row & 7) << 4)));
    }
    #pragma unroll
    for (int nt2 = 0; nt2 < 2; nt2++) {
        int row = warpN + nt2 * 16 + aRowIn;
        offB0[nt2] = (uint32_t)(row * 128 + (kHalf ^ ((row & 7) << 4)));
    }

    float acc[4][4][4];
    #pragma unroll
    for (int i = 0; i < 4; i++)
        #pragma unroll
        for (int j = 0; j < 4; j++)
            #pragma unroll
            for (int k = 0; k < 4; k++)
                acc[i][j][k] = 0.0f;

    // ---- pipelined global->smem loads ----
    auto load_stage = [&](int stage) {
        const uint32_t st = sbase + stage * STAGE_B;
        #pragma unroll
        for (int it = 0; it < 4; it++)
            cp_async16(st + swB + it * 4096, gA + it * itStride);
        #pragma unroll
        for (int it = 0; it < 4; it++)
            cp_async16(st + TILE_A + swB + it * 4096, gB + it * itStride);
        gA += 128; gB += 128;   // next 64-element K chunk
        cp_commit();
    };

    // fragment double buffers (parity = ks & 1)
    uint32_t fa[2][4][4], fb[2][4][2];

    load_stage(0);
    load_stage(1);
    cp_wait<1>();
    __syncthreads();
    prefetch_frags<0>(sbase, offA0, offB0, fa[0], fb[0]);   // chunk 0, ks0

    int sCompute = 0, sLoad = 2;
    for (int c = 0; c < NC; c++) {
        const uint32_t st = sbase + sCompute * STAGE_B;

        prefetch_frags<1>(st, offA0, offB0, fa[1], fb[1]);
        compute_frags(acc, fa[0], fb[0]);                    // ks0
        prefetch_frags<2>(st, offA0, offB0, fa[0], fb[0]);
        compute_frags(acc, fa[1], fb[1]);                    // ks1
        prefetch_frags<3>(st, offA0, offB0, fa[1], fb[1]);
        compute_frags(acc, fa[0], fb[0]);                    // ks2

        if (c + 1 < NC) {
            cp_wait<0>();          // all issued stages complete (incl. chunk c+1)
            __syncthreads();       // visibility + safe reuse of stage (c-1)%3
            if (c + 2 < NC) {
                load_stage(sLoad);
                if (++sLoad == NSTAGE) sLoad = 0;
            }
            const int sNext = (sCompute + 1 == NSTAGE) ? 0 : sCompute + 1;
            prefetch_frags<0>(sbase + sNext * STAGE_B, offA0, offB0, fa[0], fb[0]);
        }
        compute_frags(acc, fa[1], fb[1]);                    // ks3

        if (++sCompute == NSTAGE) sCompute = 0;
    }

    // ---- epilogue ----
    const int rBase = mBase + warpM + (lane >> 2);
    const int cBase = nBase + warpN + (lane & 3) * 2;

    #pragma unroll
    for (int mt = 0; mt < 4; mt++) {
        #pragma unroll
        for (int nt = 0; nt < 4; nt++) {
            const int col = cBase + nt * 8;
            const float b0 = bias[col];
            const float b1 = bias[col + 1];
            #pragma unroll
            for (int h = 0; h < 2; h++) {
                const int row = rBase + mt * 16 + h * 8;
                float v0 = acc[mt][nt][2 * h]     + b0;
                float v1 = acc[mt][nt][2 * h + 1] + b1;
                if (EPI == 0) {
                    v0 = v0 / (1.0f + expf(-v0));
                    v1 = v1 / (1.0f + expf(-v1));
                    *reinterpret_cast<__half2*>(OutH + (size_t)row * ldOut + col) =
                        __halves2half2(__float2half_rn(v0), __float2half_rn(v1));
                } else {
                    *reinterpret_cast<float2*>(OutF + (size_t)row * ldOut + col) = make_float2(v0, v1);
                }
            }
        }
    }
}

// ---------------- soft assignment (V=1 -> q = 1/(1+d2), row-normalized) ----
__global__ __launch_bounds__(256)
void soft_assign_kernel(const float* __restrict__ Z,
                        const float* __restrict__ clusters,
                        float* __restrict__ Q)
{
    __shared__ float sCl[K_CL][H1 + 1];   // +1 pad: conflict-free lane-strided reads
    const int tid = threadIdx.x;
    for (int i = tid; i < K_CL * H1; i += blockDim.x)
        sCl[i / H1][i % H1] = clusters[i];
    __syncthreads();

    const int warpId = tid >> 5;
    const int lane = tid & 31;
    const int row = blockIdx.x * 8 + warpId;
    if (row >= N_ROWS) return;

    const float* z = Z + (size_t)row * H1;
    float d2 = 0.0f;
    if (lane < K_CL) {
        #pragma unroll 8
        for (int d = 0; d < H1; d++) {
            float diff = z[d] - sCl[lane][d];
            d2 = fmaf(diff, diff, d2);
        }
    }
    float q = (lane < K_CL) ? 1.0f / (1.0f + d2) : 0.0f;
    float s = q;
    #pragma unroll
    for (int off = 16; off > 0; off >>= 1)
        s += __shfl_xor_sync(0xFFFFFFFFu, s, off);
    if (lane < K_CL)
        Q[(size_t)row * K_CL + lane] = q / s;
}

// ---------------- launch ----------------
extern "C" void kernel_launch(void* const* d_in, const int* in_sizes, int n_in,
                              void* d_out, int out_size)
{
    const float* x        = (const float*)d_in[0];
    const float* W1       = (const float*)d_in[1];
    const float* b1       = (const float*)d_in[2];
    const float* W2       = (const float*)d_in[3];
    const float* b2       = (const float*)d_in[4];
    const float* clusters = (const float*)d_in[5];

    float* z_out = (float*)d_out;
    float* q_out = (float*)d_out + (size_t)N_ROWS * H1;

    __half *xh, *w1t, *hh, *w2t;
    cudaGetSymbolAddress((void**)&xh,  g_xh);
    cudaGetSymbolAddress((void**)&w1t, g_w1t);
    cudaGetSymbolAddress((void**)&hh,  g_hh);
    cudaGetSymbolAddress((void**)&w2t, g_w2t);

    cudaFuncSetAttribute(gemm_mma_kernel<0>, cudaFuncAttributeMaxDynamicSharedMemorySize, GEMM_SMEM);
    cudaFuncSetAttribute(gemm_mma_kernel<1>, cudaFuncAttributeMaxDynamicSharedMemorySize, GEMM_SMEM);

    // 1) convert inputs to fp16
    convert_x_kernel<<<N_ROWS, 256>>>(x, xh);
    transpose_kernel<<<dim3(KPAD1 / 32, H0 / 32), dim3(32, 8)>>>(W1, w1t, D_IN, H0, KPAD1);
    transpose_kernel<<<dim3(H0 / 32, H1 / 32), dim3(32, 8)>>>(W2, w2t, H0, H1, H0);

    // 2) GEMM1: H = silu(x @ W1 + b1) -> fp16
    gemm_mma_kernel<0><<<dim3(H0 / 128, N_ROWS / 128), 256, GEMM_SMEM>>>(
        xh, w1t, b1, hh, nullptr, KPAD1, KPAD1 / 64, H0);

    // 3) GEMM2: z = H @ W2 + b2 -> fp32
    gemm_mma_kernel<1><<<dim3(H1 / 128, N_ROWS / 128), 256, GEMM_SMEM>>>(
        hh, w2t, b2, nullptr, z_out, H0, H0 / 64, H1);

    // 4) soft assignment
    soft_assign_kernel<<<N_ROWS / 8, 256>>>(z_out, clusters, q_out);
}

// round 10
// speedup vs baseline: 1.0117x; 1.0117x over previous
#include <cuda_runtime.h>
#include <cuda_fp16.h>
#include <math.h>
#include <stdint.h>

#define N_ROWS 32768
#define D_IN   3000
#define KPAD1  3072
#define H0     1024
#define H1     256
#define K_CL   20

// ---------------- scratch (static device arrays; no allocs) ----------------
__device__ __align__(16) __half g_xh[(size_t)N_ROWS * KPAD1];
__device__ __align__(16) __half g_w1t[(size_t)H0 * KPAD1];
__device__ __align__(16) __half g_hh[(size_t)N_ROWS * H0];
__device__ __align__(16) __half g_w2t[(size_t)H1 * H0];

// ---------------- helpers ----------------
__device__ __forceinline__ uint32_t smem_u32(const void* p) {
    uint32_t a;
    asm("{ .reg .u64 t; cvta.to.shared.u64 t, %1; cvt.u32.u64 %0, t; }" : "=r"(a) : "l"(p));
    return a;
}
__device__ __forceinline__ void cp_async16(uint32_t s, const void* g) {
    asm volatile("cp.async.cg.shared.global [%0], [%1], 16;" :: "r"(s), "l"(g));
}
__device__ __forceinline__ void ldm_x4(uint32_t* r, uint32_t addr) {
    asm volatile("ldmatrix.sync.aligned.m8n8.x4.shared.b16 {%0,%1,%2,%3}, [%4];"
        : "=r"(r[0]), "=r"(r[1]), "=r"(r[2]), "=r"(r[3]) : "r"(addr));
}
__device__ __forceinline__ void mma_f16(float* c, const uint32_t* a, const uint32_t* b) {
    asm volatile(
        "mma.sync.aligned.m16n8k16.row.col.f32.f16.f16.f32 "
        "{%0,%1,%2,%3}, {%4,%5,%6,%7}, {%8,%9}, {%0,%1,%2,%3};"
        : "+f"(c[0]), "+f"(c[1]), "+f"(c[2]), "+f"(c[3])
        : "r"(a[0]), "r"(a[1]), "r"(a[2]), "r"(a[3]), "r"(b[0]), "r"(b[1]));
}

// ---- mbarrier (sm_80/sm_90 base PTX; legal on compute_103) ----
#define MBAR_INIT(a, c) \
    asm volatile("mbarrier.init.shared.b64 [%0], %1;" :: "r"(a), "r"(c) : "memory")
#define MBAR_ARRIVE(a) \
    asm volatile("mbarrier.arrive.shared.b64 _, [%0];" :: "r"(a) : "memory")
#define CP_ASYNC_MBAR_ARRIVE(a) \
    asm volatile("cp.async.mbarrier.arrive.noinc.shared.b64 [%0];" :: "r"(a) : "memory")

__device__ __forceinline__ void mbar_wait_acq(uint32_t mbar, uint32_t parity) {
    uint32_t done;
    asm volatile(
        "{\n\t.reg .pred p;\n\t"
        "mbarrier.try_wait.parity.acquire.cta.shared::cta.b64 p, [%1], %2;\n\t"
        "selp.b32 %0, 1, 0, p;\n\t}"
        : "=r"(done) : "r"(mbar), "r"(parity) : "memory");
    if (!done) {
        asm volatile(
            "{\n\t.reg .pred P1;\n\t"
            "WL_%=:\n\t"
            "mbarrier.try_wait.parity.acquire.cta.shared::cta.b64 P1, [%0], %1, 0x989680;\n\t"
            "@P1 bra.uni WD_%=;\n\t"
            "bra.uni WL_%=;\n\t"
            "WD_%=:\n\t}"
            :: "r"(mbar), "r"(parity) : "memory");
    }
}
__device__ __forceinline__ void mbar_wait_relaxed(uint32_t mbar, uint32_t parity) {
    uint32_t done;
    asm volatile(
        "{\n\t.reg .pred p;\n\t"
        "mbarrier.try_wait.parity.relaxed.cta.shared::cta.b64 p, [%1], %2, 0x989680;\n\t"
        "selp.b32 %0, 1, 0, p;\n\t}"
        : "=r"(done) : "r"(mbar), "r"(parity) : "memory");
    if (!done) {
        asm volatile(
            "{\n\t.reg .pred P1;\n\t"
            "WL_%=:\n\t"
            "mbarrier.try_wait.parity.relaxed.cta.shared::cta.b64 P1, [%0], %1, 0x989680;\n\t"
            "@P1 bra.uni WD_%=;\n\t"
            "bra.uni WL_%=;\n\t"
            "WD_%=:\n\t}"
            :: "r"(mbar), "r"(parity) : "memory");
    }
}

// ---------------- preprocess kernels ----------------
__global__ __launch_bounds__(256)
void convert_x_kernel(const float* __restrict__ x,
                      __half* __restrict__ xh)
{
    const int row = blockIdx.x;
    const float* xr = x + (size_t)row * D_IN;
    __half* oh = xh + (size_t)row * KPAD1;
    for (int p = threadIdx.x; p < KPAD1 / 2; p += 256) {
        int c = p * 2;
        float v0 = 0.f, v1 = 0.f;
        if (c < D_IN) {
            float2 v = *reinterpret_cast<const float2*>(xr + c);
            v0 = v.x; v1 = v.y;
        }
        *reinterpret_cast<__half2*>(oh + c) =
            __halves2half2(__float2half_rn(v0), __float2half_rn(v1));
    }
}

// W [K, N] fp32 -> Wt [N, Kpad] fp16 (transposed, zero-padded K)
__global__ __launch_bounds__(256)
void transpose_kernel(const float* __restrict__ W,
                      __half* __restrict__ T,
                      int K, int N, int Kpad)
{
    __shared__ float s[32][33];
    const int k0 = blockIdx.x * 32;
    const int n0 = blockIdx.y * 32;
    const int tx = threadIdx.x, ty = threadIdx.y;
    #pragma unroll
    for (int j = 0; j < 32; j += 8) {
        int k = k0 + ty + j;
        s[ty + j][tx] = (k < K) ? W[(size_t)k * N + n0 + tx] : 0.0f;
    }
    __syncthreads();
    #pragma unroll
    for (int j = 0; j < 32; j += 8) {
        int n = n0 + ty + j;
        int kk = k0 + tx;
        T[(size_t)n * Kpad + kk] = __float2half_rn(s[tx][ty + j]);
    }
}

// ---------------- warp-specialized HMMA fp16 GEMM ----------------
// 8 consumer warps: CTA tile 128x128, warp tile 64x32, K-chunk 64 fp16.
// 1 producer warp: all cp.async + cp.async.mbarrier.arrive.
// 3 stages x 32KB + full/empty mbarrier rings. NO __syncthreads in mainloop.
#define TILE_A   16384
#define STAGE_B  32768
#define NSTAGE   3
#define MBAR_OFF (NSTAGE * STAGE_B)           // 98304
#define GEMM_SMEM (MBAR_OFF + 64)             // stages + barriers

// EPI=0: bias+SiLU -> fp16.  EPI=1: bias -> fp32.
template <int EPI>
__global__ __launch_bounds__(288, 2)
void gemm_mma_kernel(const __half* __restrict__ A,
                     const __half* __restrict__ B,
                     const float* __restrict__ bias,
                     __half* __restrict__ OutH,
                     float* __restrict__ OutF,
                     int Kpad, int NC, int ldOut)
{
    extern __shared__ char smem[];
    const uint32_t sbase = smem_u32(smem);
    const int tid  = threadIdx.x;
    const int wid  = tid >> 5;
    const int lane = tid & 31;
    const int mBase = blockIdx.y * 128;
    const int nBase = blockIdx.x * 128;

    // mbarriers: full[s] = MBAR_OFF + s*8, empty[s] = MBAR_OFF+24 + s*8
    if (tid == 0) {
        #pragma unroll
        for (int s = 0; s < NSTAGE; s++) {
            MBAR_INIT(sbase + MBAR_OFF + s * 8, 32);        // full: 32 producer threads
            MBAR_INIT(sbase + MBAR_OFF + 24 + s * 8, 256);  // empty: 256 consumer threads
        }
    }
    __syncthreads();

    if (wid == 8) {
        // ================= producer warp =================
        const int r0  = lane >> 3;            // 0..3
        const int c16 = lane & 7;
        const char* gA = (const char*)(A + (size_t)(mBase + r0) * Kpad) + c16 * 16;
        const char* gB = (const char*)(B + (size_t)(nBase + r0) * Kpad) + c16 * 16;
        const size_t rowStride4 = (size_t)4 * Kpad * sizeof(__half);
        // swizzled offset for row r, 16B col c16: r*128 + ((c16*16) ^ ((r&7)<<4))
        uint32_t swE = (uint32_t)(r0 * 128 + ((c16 * 16) ^ ((r0 & 7) << 4)));          // it even
        uint32_t swO = (uint32_t)((r0 + 4) * 128 + ((c16 * 16) ^ (((r0 + 4) & 7) << 4))) - 512; // it odd, minus it*512 base

        int ps = 0, pph = 1;
        for (int c = 0; c < NC; c++) {
            const uint32_t mbE = sbase + MBAR_OFF + 24 + ps * 8;
            const uint32_t mbF = sbase + MBAR_OFF + ps * 8;
            mbar_wait_relaxed(mbE, pph);
            const uint32_t st = sbase + ps * STAGE_B;
            #pragma unroll 8
            for (int it = 0; it < 32; it++) {
                uint32_t sw = ((it & 1) ? swO : swE) + it * 512;
                cp_async16(st + sw, gA + it * rowStride4);
                cp_async16(st + TILE_A + sw, gB + it * rowStride4);
            }
            CP_ASYNC_MBAR_ARRIVE(mbF);
            gA += 128; gB += 128;
            if (++ps == NSTAGE) { ps = 0; pph ^= 1; }
        }
        return;
    }

    // ================= consumer warps (0..7) =================
    const int warpM = (wid & 1) * 64;    // 0 / 64
    const int warpN = (wid >> 1) * 32;   // 0..96

    const int aRowIn = lane & 15;
    const int kHalf  = (lane >> 4) << 4;
    uint32_t offA0[4], offB0[2];
    #pragma unroll
    for (int mt = 0; mt < 4; mt++) {
        int row = warpM + mt * 16 + aRowIn;
        offA0[mt] = (uint32_t)(row * 128 + (kHalf ^ ((row & 7) << 4)));
    }
    #pragma unroll
    for (int nt2 = 0; nt2 < 2; nt2++) {
        int row = warpN + nt2 * 16 + aRowIn;
        offB0[nt2] = (uint32_t)(row * 128 + (kHalf ^ ((row & 7) << 4)));
    }

    float acc[4][4][4];
    #pragma unroll
    for (int i = 0; i < 4; i++)
        #pragma unroll
        for (int j = 0; j < 4; j++)
            #pragma unroll
            for (int k = 0; k < 4; k++)
                acc[i][j][k] = 0.0f;

    int cs = 0, cph = 0;
    for (int c = 0; c < NC; c++) {
        mbar_wait_acq(sbase + MBAR_OFF + cs * 8, cph);
        const uint32_t st = sbase + cs * STAGE_B;

        #pragma unroll
        for (int ks = 0; ks < 4; ks++) {
            const uint32_t kx = ks * 32;
            uint32_t fa[4][4], fb[4][2];
            #pragma unroll
            for (int mt = 0; mt < 4; mt++)
                ldm_x4(fa[mt], (st + offA0[mt]) ^ kx);
            #pragma unroll
            for (int nt2 = 0; nt2 < 2; nt2++) {
                uint32_t r[4];
                ldm_x4(r, (st + TILE_A + offB0[nt2]) ^ kx);
                fb[nt2 * 2][0] = r[0]; fb[nt2 * 2][1] = r[2];
                fb[nt2 * 2 + 1][0] = r[1]; fb[nt2 * 2 + 1][1] = r[3];
            }
            #pragma unroll
            for (int mt = 0; mt < 4; mt++)
                #pragma unroll
                for (int nt = 0; nt < 4; nt++)
                    mma_f16(acc[mt][nt], fa[mt], fb[nt]);
        }

        MBAR_ARRIVE(sbase + MBAR_OFF + 24 + cs * 8);
        if (++cs == NSTAGE) { cs = 0; cph ^= 1; }
    }

    // ---- epilogue ----
    const int rBase = mBase + warpM + (lane >> 2);
    const int cBase = nBase + warpN + (lane & 3) * 2;

    #pragma unroll
    for (int mt = 0; mt < 4; mt++) {
        #pragma unroll
        for (int nt = 0; nt < 4; nt++) {
            const int col = cBase + nt * 8;
            const float b0 = bias[col];
            const float b1 = bias[col + 1];
            #pragma unroll
            for (int h = 0; h < 2; h++) {
                const int row = rBase + mt * 16 + h * 8;
                float v0 = acc[mt][nt][2 * h]     + b0;
                float v1 = acc[mt][nt][2 * h + 1] + b1;
                if (EPI == 0) {
                    v0 = v0 / (1.0f + expf(-v0));
                    v1 = v1 / (1.0f + expf(-v1));
                    *reinterpret_cast<__half2*>(OutH + (size_t)row * ldOut + col) =
                        __halves2half2(__float2half_rn(v0), __float2half_rn(v1));
                } else {
                    *reinterpret_cast<float2*>(OutF + (size_t)row * ldOut + col) = make_float2(v0, v1);
                }
            }
        }
    }
}

// ---------------- soft assignment (V=1 -> q = 1/(1+d2), row-normalized) ----
__global__ __launch_bounds__(256)
void soft_assign_kernel(const float* __restrict__ Z,
                        const float* __restrict__ clusters,
                        float* __restrict__ Q)
{
    __shared__ float sCl[K_CL][H1 + 1];
    const int tid = threadIdx.x;
    for (int i = tid; i < K_CL * H1; i += blockDim.x)
        sCl[i / H1][i % H1] = clusters[i];
    __syncthreads();

    const int warpId = tid >> 5;
    const int lane = tid & 31;
    const int row = blockIdx.x * 8 + warpId;
    if (row >= N_ROWS) return;

    const float* z = Z + (size_t)row * H1;
    float d2 = 0.0f;
    if (lane < K_CL) {
        #pragma unroll 8
        for (int d = 0; d < H1; d++) {
            float diff = z[d] - sCl[lane][d];
            d2 = fmaf(diff, diff, d2);
        }
    }
    float q = (lane < K_CL) ? 1.0f / (1.0f + d2) : 0.0f;
    float s = q;
    #pragma unroll
    for (int off = 16; off > 0; off >>= 1)
        s += __shfl_xor_sync(0xFFFFFFFFu, s, off);
    if (lane < K_CL)
        Q[(size_t)row * K_CL + lane] = q / s;
}

// ---------------- launch ----------------
extern "C" void kernel_launch(void* const* d_in, const int* in_sizes, int n_in,
                              void* d_out, int out_size)
{
    const float* x        = (const float*)d_in[0];
    const float* W1       = (const float*)d_in[1];
    const float* b1       = (const float*)d_in[2];
    const float* W2       = (const float*)d_in[3];
    const float* b2       = (const float*)d_in[4];
    const float* clusters = (const float*)d_in[5];

    float* z_out = (float*)d_out;
    float* q_out = (float*)d_out + (size_t)N_ROWS * H1;

    __half *xh, *w1t, *hh, *w2t;
    cudaGetSymbolAddress((void**)&xh,  g_xh);
    cudaGetSymbolAddress((void**)&w1t, g_w1t);
    cudaGetSymbolAddress((void**)&hh,  g_hh);
    cudaGetSymbolAddress((void**)&w2t, g_w2t);

    cudaFuncSetAttribute(gemm_mma_kernel<0>, cudaFuncAttributeMaxDynamicSharedMemorySize, GEMM_SMEM);
    cudaFuncSetAttribute(gemm_mma_kernel<1>, cudaFuncAttributeMaxDynamicSharedMemorySize, GEMM_SMEM);

    // 1) convert inputs to fp16
    convert_x_kernel<<<N_ROWS, 256>>>(x, xh);
    transpose_kernel<<<dim3(KPAD1 / 32, H0 / 32), dim3(32, 8)>>>(W1, w1t, D_IN, H0, KPAD1);
    transpose_kernel<<<dim3(H0 / 32, H1 / 32), dim3(32, 8)>>>(W2, w2t, H0, H1, H0);

    // 2) GEMM1: H = silu(x @ W1 + b1) -> fp16
    gemm_mma_kernel<0><<<dim3(H0 / 128, N_ROWS / 128), 288, GEMM_SMEM>>>(
        xh, w1t, b1, hh, nullptr, KPAD1, KPAD1 / 64, H0);

    // 3) GEMM2: z = H @ W2 + b2 -> fp32
    gemm_mma_kernel<1><<<dim3(H1 / 128, N_ROWS / 128), 288, GEMM_SMEM>>>(
        hh, w2t, b2, nullptr, z_out, H0, H0 / 64, H1);

    // 4) soft assignment
    soft_assign_kernel<<<N_ROWS / 8, 256>>>(z_out, clusters, q_out);
}